// round 3
// baseline (speedup 1.0000x reference)
#include <cuda_runtime.h>

#define N_NODES 100000
#define N_EDGES 1600000
#define D 128
#define NV4 (D/4)   // 32 float4 per row

// ---------------- scratch (device globals; no allocation allowed) ----------------
__device__ int    g_deg[N_NODES];
__device__ int    g_fill[N_NODES];
__device__ int    g_rowptr[N_NODES + 1];
__device__ int    g_csr_src[N_EDGES];
__device__ float  g_deginv[N_NODES];
__device__ float4 g_agg[(size_t)N_NODES * NV4];   // 51.2 MB
__device__ float4 g_h[(size_t)N_NODES * NV4];     // 51.2 MB

// ---------------- CSR build ----------------
__global__ void k_zero() {
    int i = blockIdx.x * blockDim.x + threadIdx.x;
    if (i < N_NODES) { g_deg[i] = 0; g_fill[i] = 0; }
}

__global__ void k_hist(const int* __restrict__ ei) {
    int e = blockIdx.x * blockDim.x + threadIdx.x;
    if (e < N_EDGES) atomicAdd(&g_deg[ei[N_EDGES + e]], 1);
}

// single-block exclusive scan of g_deg -> g_rowptr (N=100k, trivial cost)
__global__ void k_scan() {
    __shared__ int ss[1024];
    int t = threadIdx.x;
    const int CH = (N_NODES + 1023) / 1024;   // 98
    int b0 = t * CH;
    int b1 = min(b0 + CH, N_NODES);
    int s = 0;
    for (int i = b0; i < b1; i++) s += g_deg[i];
    ss[t] = s;
    __syncthreads();
    for (int off = 1; off < 1024; off <<= 1) {
        int v = (t >= off) ? ss[t - off] : 0;
        __syncthreads();
        ss[t] += v;
        __syncthreads();
    }
    int excl = (t == 0) ? 0 : ss[t - 1];
    for (int i = b0; i < b1; i++) { g_rowptr[i] = excl; excl += g_deg[i]; }
    if (t == 1023) g_rowptr[N_NODES] = excl;   // == N_EDGES
}

__global__ void k_deginv() {
    int i = blockIdx.x * blockDim.x + threadIdx.x;
    if (i < N_NODES) {
        int d = g_deg[i];
        g_deginv[i] = (d > 0) ? (1.0f / (float)d) : 0.0f;
    }
}

__global__ void k_fill(const int* __restrict__ ei) {
    int e = blockIdx.x * blockDim.x + threadIdx.x;
    if (e < N_EDGES) {
        int dst = ei[N_EDGES + e];
        int p = atomicAdd(&g_fill[dst], 1);
        g_csr_src[g_rowptr[dst] + p] = ei[e];
    }
}

// edge_index passthrough as float32 (harness output buffer is float32)
__global__ void k_edgecast(const int* __restrict__ ei, float* __restrict__ out) {
    int i = blockIdx.x * blockDim.x + threadIdx.x;
    if (i < 2 * N_EDGES) out[i] = (float)ei[i];
}

// ---------------- mean aggregation: one warp per node ----------------
// LAYER==1: read external x; LAYER==2: read g_h. Always writes g_agg.
template <int LAYER>
__global__ void k_agg(const float4* __restrict__ Xext) {
    const float4* __restrict__ xin = (LAYER == 1) ? Xext : (const float4*)g_h;
    int gw   = (blockIdx.x * blockDim.x + threadIdx.x) >> 5;
    int lane = threadIdx.x & 31;
    if (gw >= N_NODES) return;
    int e0 = g_rowptr[gw];
    int e1 = g_rowptr[gw + 1];
    float4 acc = make_float4(0.f, 0.f, 0.f, 0.f);
    for (int e = e0; e < e1; e++) {
        int s = g_csr_src[e];
        float4 v = xin[(size_t)s * NV4 + lane];
        acc.x += v.x; acc.y += v.y; acc.z += v.z; acc.w += v.w;
    }
    float di = g_deginv[gw];
    acc.x *= di; acc.y *= di; acc.z *= di; acc.w *= di;
    g_agg[(size_t)gw * NV4 + lane] = acc;
}

// ---------------- fused SAGE linear: out = agg@Wl + root@Wr + b (+ReLU) ----------
// 64 rows x 128 cols per block, 256 threads, each thread 4x8 outputs.
// LAYER==1: root = Xext, out = g_h, ReLU. LAYER==2: root = g_h, out = Oext.
template <int LAYER>
__global__ void __launch_bounds__(256) k_gemm(
    const float* __restrict__ Xext,
    const float* __restrict__ Wl, const float* __restrict__ Wr,
    const float* __restrict__ bias,
    float* __restrict__ Oext)
{
    const float* __restrict__ Aroot = (LAYER == 1) ? Xext : (const float*)g_h;
    float* __restrict__ out = (LAYER == 1) ? (float*)g_h : Oext;

    __shared__ float  As[64][33];
    __shared__ float4 Ws[32][32];   // [k][128 floats as 32 float4]

    const int row0 = blockIdx.x * 64;
    const int tid  = threadIdx.x;
    const int tx   = tid & 15;    // cols tx*8 .. tx*8+7
    const int ty   = tid >> 4;    // rows ty*4 .. ty*4+3 (within tile)

    float acc[4][8];
#pragma unroll
    for (int i = 0; i < 4; i++)
#pragma unroll
        for (int j = 0; j < 8; j++) acc[i][j] = 0.f;

#pragma unroll 1
    for (int side = 0; side < 2; side++) {
        const float* __restrict__ A = side ? Aroot : (const float*)g_agg;
        const float* __restrict__ W = side ? Wr : Wl;
#pragma unroll 1
        for (int kc = 0; kc < 4; kc++) {
            // A tile: 64 rows x 32 k  (512 float4)
#pragma unroll
            for (int rep = 0; rep < 2; rep++) {
                int idx = tid + rep * 256;
                int r   = idx >> 3;
                int c4  = (idx & 7) * 4;
                float4 v = make_float4(0.f, 0.f, 0.f, 0.f);
                if (row0 + r < N_NODES)
                    v = *(const float4*)(A + (size_t)(row0 + r) * D + kc * 32 + c4);
                As[r][c4 + 0] = v.x; As[r][c4 + 1] = v.y;
                As[r][c4 + 2] = v.z; As[r][c4 + 3] = v.w;
            }
            // W tile: 32 k x 128 cols (1024 float4)
#pragma unroll
            for (int rep = 0; rep < 4; rep++) {
                int idx = tid + rep * 256;
                int kr  = idx >> 5;
                int c4  = idx & 31;
                Ws[kr][c4] = *(const float4*)(W + (size_t)(kc * 32 + kr) * D + c4 * 4);
            }
            __syncthreads();
#pragma unroll
            for (int k = 0; k < 32; k++) {
                float av[4];
                av[0] = As[ty * 4 + 0][k];
                av[1] = As[ty * 4 + 1][k];
                av[2] = As[ty * 4 + 2][k];
                av[3] = As[ty * 4 + 3][k];
                float4 w0 = Ws[k][tx * 2 + 0];
                float4 w1 = Ws[k][tx * 2 + 1];
                float wv[8] = {w0.x, w0.y, w0.z, w0.w, w1.x, w1.y, w1.z, w1.w};
#pragma unroll
                for (int i = 0; i < 4; i++)
#pragma unroll
                    for (int j = 0; j < 8; j++)
                        acc[i][j] += av[i] * wv[j];
            }
            __syncthreads();
        }
    }

    // epilogue: +bias (+ReLU for layer 1)
    float4 b0 = *(const float4*)(bias + tx * 8);
    float4 b1 = *(const float4*)(bias + tx * 8 + 4);
    float bv[8] = {b0.x, b0.y, b0.z, b0.w, b1.x, b1.y, b1.z, b1.w};
#pragma unroll
    for (int i = 0; i < 4; i++) {
        int row = row0 + ty * 4 + i;
        if (row < N_NODES) {
            float o[8];
#pragma unroll
            for (int j = 0; j < 8; j++) {
                o[j] = acc[i][j] + bv[j];
                if (LAYER == 1) o[j] = fmaxf(o[j], 0.f);
            }
            float4 v0 = make_float4(o[0], o[1], o[2], o[3]);
            float4 v1 = make_float4(o[4], o[5], o[6], o[7]);
            *(float4*)(out + (size_t)row * D + tx * 8 + 0) = v0;
            *(float4*)(out + (size_t)row * D + tx * 8 + 4) = v1;
        }
    }
}

// ---------------- launch ----------------
extern "C" void kernel_launch(void* const* d_in, const int* in_sizes, int n_in,
                              void* d_out, int out_size)
{
    const float* x   = (const float*)d_in[0];
    const float* W1l = (const float*)d_in[1];
    const float* b1  = (const float*)d_in[2];
    const float* W1r = (const float*)d_in[3];
    const float* W2l = (const float*)d_in[4];
    const float* b2  = (const float*)d_in[5];
    const float* W2r = (const float*)d_in[6];
    const int*   ei  = (const int*)d_in[7];
    float* out = (float*)d_out;

    const int TB = 256;

    // CSR build + degrees
    k_zero<<<(N_NODES + TB - 1) / TB, TB>>>();
    k_hist<<<(N_EDGES + TB - 1) / TB, TB>>>(ei);
    k_scan<<<1, 1024>>>();
    k_deginv<<<(N_NODES + TB - 1) / TB, TB>>>();
    k_fill<<<(N_EDGES + TB - 1) / TB, TB>>>(ei);

    const int aggBlocks  = (N_NODES * 32 + TB - 1) / TB;
    const int gemmBlocks = (N_NODES + 63) / 64;

    // layer 1
    k_agg<1><<<aggBlocks, TB>>>((const float4*)x);
    k_gemm<1><<<gemmBlocks, TB>>>(x, W1l, W1r, b1, nullptr);

    // layer 2
    k_agg<2><<<aggBlocks, TB>>>(nullptr);
    k_gemm<2><<<gemmBlocks, TB>>>(nullptr, W2l, W2r, b2, out);

    // tail of output tuple: edge_index passthrough cast to float32
    k_edgecast<<<(2 * N_EDGES + TB - 1) / TB, TB>>>(ei, out + (size_t)N_NODES * D);
}

// round 5
// speedup vs baseline: 1.7565x; 1.7565x over previous
#include <cuda_runtime.h>
#include <cuda_bf16.h>
#include <mma.h>
#include <cstdint>

using namespace nvcuda;

#define N_NODES 100000
#define N_PAD   100096           // padded row count for internal buffers
#define N_EDGES 1600000
#define D 128
#define NV4 (D/4)

// ---------------- scratch (device globals; no allocation allowed) ----------------
__device__ int    g_deg[N_NODES];
__device__ int    g_fill[N_NODES];
__device__ int    g_rowptr[N_NODES + 1];
__device__ int    g_csr_src[N_EDGES];
__device__ float  g_deginv[N_NODES];
__device__ float4 g_agg[(size_t)N_PAD * NV4];   // fp32 aggregated (padded)
__device__ float4 g_h[(size_t)N_PAD * NV4];     // fp32 hidden (padded)
// weight images: [mat 0..3][hi=0/lo=1][K=128][N=128] bf16 row-major
__device__ __align__(16) __nv_bfloat16 g_Wimg[4][2][128 * 128];

// ---------------- CSR build ----------------
__global__ void k_zero() {
    int i = blockIdx.x * blockDim.x + threadIdx.x;
    if (i < N_NODES) { g_deg[i] = 0; g_fill[i] = 0; }
}
__global__ void k_hist(const int* __restrict__ ei) {
    int e = blockIdx.x * blockDim.x + threadIdx.x;
    if (e < N_EDGES) atomicAdd(&g_deg[ei[N_EDGES + e]], 1);
}
__global__ void k_scan() {
    __shared__ int ss[1024];
    int t = threadIdx.x;
    const int CH = (N_NODES + 1023) / 1024;
    int b0 = t * CH, b1 = min(b0 + CH, N_NODES);
    int s = 0;
    for (int i = b0; i < b1; i++) s += g_deg[i];
    ss[t] = s; __syncthreads();
    for (int off = 1; off < 1024; off <<= 1) {
        int v = (t >= off) ? ss[t - off] : 0;
        __syncthreads(); ss[t] += v; __syncthreads();
    }
    int excl = (t == 0) ? 0 : ss[t - 1];
    for (int i = b0; i < b1; i++) { g_rowptr[i] = excl; excl += g_deg[i]; }
    if (t == 1023) g_rowptr[N_NODES] = excl;
}
__global__ void k_deginv() {
    int i = blockIdx.x * blockDim.x + threadIdx.x;
    if (i < N_NODES) {
        int d = g_deg[i];
        g_deginv[i] = (d > 0) ? (1.0f / (float)d) : 0.0f;
    }
}
__global__ void k_fill(const int* __restrict__ ei) {
    int e = blockIdx.x * blockDim.x + threadIdx.x;
    if (e < N_EDGES) {
        int dst = ei[N_EDGES + e];
        int p = atomicAdd(&g_fill[dst], 1);
        g_csr_src[g_rowptr[dst] + p] = ei[e];
    }
}
__global__ void k_edgecast(const int* __restrict__ ei, float* __restrict__ out) {
    int i = blockIdx.x * blockDim.x + threadIdx.x;
    if (i < 2 * N_EDGES) out[i] = (float)ei[i];
}

// ---------------- weight prep: fp32 [K][N] -> bf16 hi/lo row-major images ----------
__global__ void k_wprep(const float* __restrict__ W0, const float* __restrict__ W1,
                        const float* __restrict__ W2, const float* __restrict__ W3) {
    const float* W = (blockIdx.x == 0) ? W0 : (blockIdx.x == 1) ? W1
                   : (blockIdx.x == 2) ? W2 : W3;
    __nv_bfloat16* hi = &g_Wimg[blockIdx.x][0][0];
    __nv_bfloat16* lo = &g_Wimg[blockIdx.x][1][0];
    for (int idx = threadIdx.x; idx < 128 * 128; idx += blockDim.x) {
        float v = W[idx];
        __nv_bfloat16 h = __float2bfloat16(v);
        hi[idx] = h;
        lo[idx] = __float2bfloat16(v - __bfloat162float(h));
    }
}

// ---------------- mean aggregation: one warp per node ----------------
template <int LAYER>
__global__ void k_agg(const float4* __restrict__ Xext) {
    const float4* __restrict__ xin = (LAYER == 1) ? Xext : (const float4*)g_h;
    int gw = (blockIdx.x * blockDim.x + threadIdx.x) >> 5;
    int lane = threadIdx.x & 31;
    if (gw >= N_NODES) return;
    int e0 = g_rowptr[gw], e1 = g_rowptr[gw + 1];
    float4 acc = make_float4(0.f, 0.f, 0.f, 0.f);
    for (int e = e0; e < e1; e++) {
        int s = g_csr_src[e];
        float4 v = xin[(size_t)s * NV4 + lane];
        acc.x += v.x; acc.y += v.y; acc.z += v.z; acc.w += v.w;
    }
    float di = g_deginv[gw];
    acc.x *= di; acc.y *= di; acc.z *= di; acc.w *= di;
    g_agg[(size_t)gw * NV4 + lane] = acc;
}

// ---------------- WMMA bf16-split fused SAGE linear ----------------
// out[128x128 tile] = agg@Wl + root@Wr + bias (+ReLU layer1)
// 8 warps in 4x2 grid; each warp: 2x4 wmma 16x16x16 tiles (32 rows x 64 cols).
#define LDA 136    // bf16 smem leading dim (mult of 8)
#define LDB 136
#define LDC 132    // f32 bounce leading dim (mult of 4)
#define SM_BIAS   (16 * 136 * 4)                     // 8704 B
#define SM_TILE   (128 * 136 * 2)                    // 34816 B per bf16 tile
#define SMEM_REQ  (SM_BIAS + 4 * SM_TILE)            // 147968 B

__device__ __forceinline__ uint32_t pack_bf2(float a, float b) {
    return ((uint32_t)__bfloat16_as_ushort(__float2bfloat16(b)) << 16) |
           (uint32_t)__bfloat16_as_ushort(__float2bfloat16(a));
}

template <int LAYER>
__global__ void __launch_bounds__(256, 1) k_wgemm(
    const float* __restrict__ RootExt,
    const float* __restrict__ bias,
    float* __restrict__ OutExt,
    int wl, int wr)
{
    extern __shared__ char smem[];
    float* bias_rep = (float*)smem;
    __nv_bfloat16* Ah = (__nv_bfloat16*)(smem + SM_BIAS);
    __nv_bfloat16* Al = Ah + 128 * LDA;
    __nv_bfloat16* Bh = Al + 128 * LDA;
    __nv_bfloat16* Bl = Bh + 128 * LDB;

    const float* __restrict__ Aroot = (LAYER == 1) ? RootExt : (const float*)g_h;
    float* __restrict__ out = (LAYER == 1) ? (float*)g_h : OutExt;

    const int tid = threadIdx.x;
    const int wid = tid >> 5;
    const int row0 = blockIdx.x * 128;
    const int wy = wid >> 1;       // 0..3  -> rows wy*32
    const int wx = wid & 1;        // 0..1  -> cols wx*64

    // replicated bias tile (16 rows x 128 cols)
    for (int i = tid; i < 16 * 128; i += 256) {
        int r = i >> 7, c = i & 127;
        bias_rep[r * 136 + c] = bias[c];
    }
    __syncthreads();

    wmma::fragment<wmma::accumulator, 16, 16, 16, float> acc[2][4];
#pragma unroll
    for (int i = 0; i < 2; i++)
#pragma unroll
        for (int j = 0; j < 4; j++)
            wmma::load_matrix_sync(acc[i][j], bias_rep + wx * 64 + j * 16, 136,
                                   wmma::mem_row_major);

#pragma unroll 1
    for (int side = 0; side < 2; side++) {
        if (side == 1) __syncthreads();   // all reads of smem from side 0 done
        const float* __restrict__ A = side ? Aroot : (const float*)g_agg;
        // A tile: fp32 -> hi/lo bf16
#pragma unroll
        for (int it = 0; it < 16; it++) {
            int idx = tid + it * 256;           // 4096 float4 slots
            int m = idx >> 5, q = idx & 31;
            float4 v = make_float4(0.f, 0.f, 0.f, 0.f);
            if (row0 + m < N_NODES)
                v = *(const float4*)(A + (size_t)(row0 + m) * D + q * 4);
            uint32_t h0 = pack_bf2(v.x, v.y), h1 = pack_bf2(v.z, v.w);
            float rx = v.x - __bfloat162float(__float2bfloat16(v.x));
            float ry = v.y - __bfloat162float(__float2bfloat16(v.y));
            float rz = v.z - __bfloat162float(__float2bfloat16(v.z));
            float rw = v.w - __bfloat162float(__float2bfloat16(v.w));
            *(uint2*)&Ah[m * LDA + q * 4] = make_uint2(h0, h1);
            *(uint2*)&Al[m * LDA + q * 4] = make_uint2(pack_bf2(rx, ry), pack_bf2(rz, rw));
        }
        // B tile copy (repad 128 -> 136)
        int mat = side ? wr : wl;
        const uint4* sh = (const uint4*)&g_Wimg[mat][0][0];
        const uint4* sl = (const uint4*)&g_Wimg[mat][1][0];
#pragma unroll
        for (int it = 0; it < 8; it++) {
            int idx = tid + it * 256;           // 2048 uint4
            int k = idx >> 4, c = idx & 15;
            *(uint4*)&Bh[k * LDB + c * 8] = sh[idx];
            *(uint4*)&Bl[k * LDB + c * 8] = sl[idx];
        }
        __syncthreads();

#pragma unroll
        for (int ks = 0; ks < 8; ks++) {
            int k0 = ks * 16;
            wmma::fragment<wmma::matrix_a, 16, 16, 16, __nv_bfloat16, wmma::row_major> ah[2], al[2];
#pragma unroll
            for (int i = 0; i < 2; i++) {
                wmma::load_matrix_sync(ah[i], Ah + (wy * 32 + i * 16) * LDA + k0, LDA);
                wmma::load_matrix_sync(al[i], Al + (wy * 32 + i * 16) * LDA + k0, LDA);
            }
#pragma unroll
            for (int j = 0; j < 4; j++) {
                int n0 = wx * 64 + j * 16;
                wmma::fragment<wmma::matrix_b, 16, 16, 16, __nv_bfloat16, wmma::row_major> bh, bl;
                wmma::load_matrix_sync(bh, Bh + k0 * LDB + n0, LDB);
                wmma::load_matrix_sync(bl, Bl + k0 * LDB + n0, LDB);
#pragma unroll
                for (int i = 0; i < 2; i++) {
                    wmma::mma_sync(acc[i][j], ah[i], bh, acc[i][j]);
                    wmma::mma_sync(acc[i][j], ah[i], bl, acc[i][j]);
                    wmma::mma_sync(acc[i][j], al[i], bh, acc[i][j]);
                }
            }
        }
    }

    // ---- epilogue ----
    if (LAYER == 1) {
#pragma unroll
        for (int i = 0; i < 2; i++)
#pragma unroll
            for (int j = 0; j < 4; j++)
#pragma unroll
                for (int t = 0; t < acc[i][j].num_elements; t++)
                    acc[i][j].x[t] = fmaxf(acc[i][j].x[t], 0.f);
    }

    bool direct = (LAYER == 1) || (row0 + 128 <= N_NODES);
    if (direct) {
        // layer1 writes g_h (padded rows exist); layer2 full tiles write harness buffer
#pragma unroll
        for (int i = 0; i < 2; i++)
#pragma unroll
            for (int j = 0; j < 4; j++)
                wmma::store_matrix_sync(
                    out + (size_t)(row0 + wy * 32 + i * 16) * D + wx * 64 + j * 16,
                    acc[i][j], D, wmma::mem_row_major);
    } else {
        // ragged last tile: bounce via smem, guarded copy
        float* bounce = (float*)smem;
        __syncthreads();   // everyone done reading A/B smem
#pragma unroll
        for (int i = 0; i < 2; i++)
#pragma unroll
            for (int j = 0; j < 4; j++)
                wmma::store_matrix_sync(
                    bounce + (size_t)(wy * 32 + i * 16) * LDC + wx * 64 + j * 16,
                    acc[i][j], LDC, wmma::mem_row_major);
        __syncthreads();
        int valid = N_NODES - row0;
        for (int idx = tid; idx < valid * 32; idx += 256) {
            int r = idx >> 5, q = idx & 31;
            float4 v = *(float4*)&bounce[r * LDC + q * 4];
            *(float4*)(out + (size_t)(row0 + r) * D + q * 4) = v;
        }
    }
}

// ---------------- launch ----------------
extern "C" void kernel_launch(void* const* d_in, const int* in_sizes, int n_in,
                              void* d_out, int out_size)
{
    const float* x   = (const float*)d_in[0];
    const float* W1l = (const float*)d_in[1];
    const float* b1  = (const float*)d_in[2];
    const float* W1r = (const float*)d_in[3];
    const float* W2l = (const float*)d_in[4];
    const float* b2  = (const float*)d_in[5];
    const float* W2r = (const float*)d_in[6];
    const int*   ei  = (const int*)d_in[7];
    float* out = (float*)d_out;

    const int TB = 256;
    cudaFuncSetAttribute(k_wgemm<1>, cudaFuncAttributeMaxDynamicSharedMemorySize, SMEM_REQ);
    cudaFuncSetAttribute(k_wgemm<2>, cudaFuncAttributeMaxDynamicSharedMemorySize, SMEM_REQ);

    // CSR build + degrees + weight prep
    k_zero<<<(N_NODES + TB - 1) / TB, TB>>>();
    k_hist<<<(N_EDGES + TB - 1) / TB, TB>>>(ei);
    k_scan<<<1, 1024>>>();
    k_deginv<<<(N_NODES + TB - 1) / TB, TB>>>();
    k_fill<<<(N_EDGES + TB - 1) / TB, TB>>>(ei);
    k_wprep<<<4, TB>>>(W1l, W1r, W2l, W2r);

    const int aggBlocks  = (N_NODES * 32 + TB - 1) / TB;
    const int gemmBlocks = (N_NODES + 127) / 128;

    // layer 1
    k_agg<1><<<aggBlocks, TB>>>((const float4*)x);
    k_wgemm<1><<<gemmBlocks, TB, SMEM_REQ>>>(x, b1, nullptr, 0, 1);

    // layer 2
    k_agg<2><<<aggBlocks, TB>>>(nullptr);
    k_wgemm<2><<<gemmBlocks, TB, SMEM_REQ>>>(nullptr, b2, out, 2, 3);

    // tail of output tuple: edge_index passthrough cast to float32
    k_edgecast<<<(2 * N_EDGES + TB - 1) / TB, TB>>>(ei, out + (size_t)N_NODES * D);
}

// round 6
// speedup vs baseline: 1.7720x; 1.0089x over previous
#include <cuda_runtime.h>
#include <cuda_bf16.h>
#include <cuda_fp16.h>
#include <mma.h>
#include <cstdint>

using namespace nvcuda;

#define N_NODES 100000
#define N_PAD   100096
#define N_EDGES 1600000
#define D 128
#define NV4 (D/4)

// ---------------- scratch (device globals; no allocation allowed) ----------------
__device__ int    g_deg[N_NODES];
__device__ int    g_fill[N_NODES];
__device__ int    g_rowptr[N_NODES + 1];
__device__ int    g_csr_src[N_EDGES];
__device__ float4 g_agg[(size_t)N_PAD * NV4];                 // fp32 aggregated
__device__ float4 g_h[(size_t)N_PAD * NV4];                   // fp32 hidden
__device__ __align__(16) __half g_xh[(size_t)N_PAD * D];      // fp16 copy of x (gather)
__device__ __align__(16) __half g_hh[(size_t)N_PAD * D];      // fp16 copy of h (gather)
// weight images: [mat 0..3][hi=0/lo=1][K=128][N=128] bf16 row-major
__device__ __align__(16) __nv_bfloat16 g_Wimg[4][2][128 * 128];

// ---------------- mega-init: zero + weight prep + edgecast + x->fp16 ----------------
#define ZB 391
#define WB 4
#define EB 3125     /* 3.2M floats / 1024 per block */
#define XB 6250     /* 12.8M floats / 2048 per block */

__global__ void k_init(const float* __restrict__ x,
                       const float* __restrict__ W0, const float* __restrict__ W1,
                       const float* __restrict__ W2, const float* __restrict__ W3,
                       const int* __restrict__ ei, float* __restrict__ outTail)
{
    int b = blockIdx.x;
    int tid = threadIdx.x;
    if (b < ZB) {
        int i = b * 256 + tid;
        if (i < N_NODES) { g_deg[i] = 0; g_fill[i] = 0; }
    } else if (b < ZB + WB) {
        int m = b - ZB;
        const float* W = (m == 0) ? W0 : (m == 1) ? W1 : (m == 2) ? W2 : W3;
        __nv_bfloat16* hi = &g_Wimg[m][0][0];
        __nv_bfloat16* lo = &g_Wimg[m][1][0];
        for (int idx = tid; idx < 128 * 128; idx += 256) {
            float v = W[idx];
            __nv_bfloat16 h = __float2bfloat16(v);
            hi[idx] = h;
            lo[idx] = __float2bfloat16(v - __bfloat162float(h));
        }
    } else if (b < ZB + WB + EB) {
        int i = (b - ZB - WB) * 1024 + tid * 4;
        int4 v = *(const int4*)(ei + i);
        *(float4*)(outTail + i) = make_float4((float)v.x, (float)v.y,
                                              (float)v.z, (float)v.w);
    } else {
        int b2 = b - ZB - WB - EB;
        const float4* xv = (const float4*)x;
        int f4 = b2 * 512 + tid * 2;
        float4 a = xv[f4], c = xv[f4 + 1];
        __half2 h0 = __floats2half2_rn(a.x, a.y);
        __half2 h1 = __floats2half2_rn(a.z, a.w);
        __half2 h2 = __floats2half2_rn(c.x, c.y);
        __half2 h3 = __floats2half2_rn(c.z, c.w);
        uint4 o;
        o.x = *(uint32_t*)&h0; o.y = *(uint32_t*)&h1;
        o.z = *(uint32_t*)&h2; o.w = *(uint32_t*)&h3;
        *(uint4*)(&g_xh[(size_t)b2 * 2048 + tid * 8]) = o;
    }
}

// ---------------- CSR build ----------------
__global__ void k_hist(const int* __restrict__ ei) {
    int e = blockIdx.x * blockDim.x + threadIdx.x;
    if (e < N_EDGES) atomicAdd(&g_deg[ei[N_EDGES + e]], 1);
}
__global__ void k_scan() {
    __shared__ int ss[1024];
    int t = threadIdx.x;
    const int CH = (N_NODES + 1023) / 1024;
    int b0 = t * CH, b1 = min(b0 + CH, N_NODES);
    int s = 0;
    for (int i = b0; i < b1; i++) s += g_deg[i];
    ss[t] = s; __syncthreads();
    for (int off = 1; off < 1024; off <<= 1) {
        int v = (t >= off) ? ss[t - off] : 0;
        __syncthreads(); ss[t] += v; __syncthreads();
    }
    int excl = (t == 0) ? 0 : ss[t - 1];
    for (int i = b0; i < b1; i++) { g_rowptr[i] = excl; excl += g_deg[i]; }
    if (t == 1023) g_rowptr[N_NODES] = excl;
}
__global__ void k_fill(const int* __restrict__ ei) {
    int e = blockIdx.x * blockDim.x + threadIdx.x;
    if (e < N_EDGES) {
        int dst = ei[N_EDGES + e];
        int p = atomicAdd(&g_fill[dst], 1);
        g_csr_src[g_rowptr[dst] + p] = ei[e];
    }
}

// ---------------- mean aggregation (fp16 gather): one warp per node ----------------
template <int LAYER>
__global__ void k_agg() {
    const uint2* __restrict__ xin =
        (const uint2*)((LAYER == 1) ? g_xh : g_hh);   // 32 uint2 per row
    int gw = (blockIdx.x * blockDim.x + threadIdx.x) >> 5;
    int lane = threadIdx.x & 31;
    if (gw >= N_NODES) return;
    int e0 = g_rowptr[gw], e1 = g_rowptr[gw + 1];
    float4 a0 = make_float4(0.f, 0.f, 0.f, 0.f);
    float4 a1 = make_float4(0.f, 0.f, 0.f, 0.f);
    int e = e0;
    for (; e + 1 < e1; e += 2) {
        int s0 = g_csr_src[e], s1 = g_csr_src[e + 1];
        uint2 v0 = xin[(size_t)s0 * 32 + lane];
        uint2 v1 = xin[(size_t)s1 * 32 + lane];
        float2 f00 = __half22float2(*(__half2*)&v0.x);
        float2 f01 = __half22float2(*(__half2*)&v0.y);
        float2 f10 = __half22float2(*(__half2*)&v1.x);
        float2 f11 = __half22float2(*(__half2*)&v1.y);
        a0.x += f00.x; a0.y += f00.y; a0.z += f01.x; a0.w += f01.y;
        a1.x += f10.x; a1.y += f10.y; a1.z += f11.x; a1.w += f11.y;
    }
    if (e < e1) {
        int s0 = g_csr_src[e];
        uint2 v0 = xin[(size_t)s0 * 32 + lane];
        float2 f00 = __half22float2(*(__half2*)&v0.x);
        float2 f01 = __half22float2(*(__half2*)&v0.y);
        a0.x += f00.x; a0.y += f00.y; a0.z += f01.x; a0.w += f01.y;
    }
    int d = e1 - e0;
    float di = (d > 0) ? (1.0f / (float)d) : 0.0f;
    float4 acc = make_float4((a0.x + a1.x) * di, (a0.y + a1.y) * di,
                             (a0.z + a1.z) * di, (a0.w + a1.w) * di);
    g_agg[(size_t)gw * NV4 + lane] = acc;
}

// ---------------- WMMA bf16-split fused SAGE linear ----------------
#define LDA 136
#define LDB 136
#define LDC 132
#define SM_BIAS   (16 * 136 * 4)
#define SM_TILE   (128 * 136 * 2)
#define SMEM_REQ  (SM_BIAS + 4 * SM_TILE)

__device__ __forceinline__ uint32_t pack_bf2(float a, float b) {
    return ((uint32_t)__bfloat16_as_ushort(__float2bfloat16(b)) << 16) |
           (uint32_t)__bfloat16_as_ushort(__float2bfloat16(a));
}

template <int LAYER>
__global__ void __launch_bounds__(256, 1) k_wgemm(
    const float* __restrict__ RootExt,
    const float* __restrict__ bias,
    float* __restrict__ OutExt,
    int wl, int wr)
{
    extern __shared__ char smem[];
    float* bias_rep = (float*)smem;
    __nv_bfloat16* Ah = (__nv_bfloat16*)(smem + SM_BIAS);
    __nv_bfloat16* Al = Ah + 128 * LDA;
    __nv_bfloat16* Bh = Al + 128 * LDA;
    __nv_bfloat16* Bl = Bh + 128 * LDB;

    const float* __restrict__ Aroot = (LAYER == 1) ? RootExt : (const float*)g_h;
    float* __restrict__ out = (LAYER == 1) ? (float*)g_h : OutExt;

    const int tid = threadIdx.x;
    const int wid = tid >> 5;
    const int row0 = blockIdx.x * 128;
    const int wy = wid >> 1;
    const int wx = wid & 1;

    for (int i = tid; i < 16 * 128; i += 256) {
        int r = i >> 7, c = i & 127;
        bias_rep[r * 136 + c] = bias[c];
    }
    __syncthreads();

    wmma::fragment<wmma::accumulator, 16, 16, 16, float> acc[2][4];
#pragma unroll
    for (int i = 0; i < 2; i++)
#pragma unroll
        for (int j = 0; j < 4; j++)
            wmma::load_matrix_sync(acc[i][j], bias_rep + wx * 64 + j * 16, 136,
                                   wmma::mem_row_major);

#pragma unroll 1
    for (int side = 0; side < 2; side++) {
        if (side == 1) __syncthreads();
        const float* __restrict__ A = side ? Aroot : (const float*)g_agg;
#pragma unroll
        for (int it = 0; it < 16; it++) {
            int idx = tid + it * 256;
            int m = idx >> 5, q = idx & 31;
            float4 v = make_float4(0.f, 0.f, 0.f, 0.f);
            if (row0 + m < N_NODES)
                v = *(const float4*)(A + (size_t)(row0 + m) * D + q * 4);
            uint32_t h0 = pack_bf2(v.x, v.y), h1 = pack_bf2(v.z, v.w);
            float rx = v.x - __bfloat162float(__float2bfloat16(v.x));
            float ry = v.y - __bfloat162float(__float2bfloat16(v.y));
            float rz = v.z - __bfloat162float(__float2bfloat16(v.z));
            float rw = v.w - __bfloat162float(__float2bfloat16(v.w));
            *(uint2*)&Ah[m * LDA + q * 4] = make_uint2(h0, h1);
            *(uint2*)&Al[m * LDA + q * 4] = make_uint2(pack_bf2(rx, ry), pack_bf2(rz, rw));
        }
        int mat = side ? wr : wl;
        const uint4* sh = (const uint4*)&g_Wimg[mat][0][0];
        const uint4* sl = (const uint4*)&g_Wimg[mat][1][0];
#pragma unroll
        for (int it = 0; it < 8; it++) {
            int idx = tid + it * 256;
            int k = idx >> 4, c = idx & 15;
            *(uint4*)&Bh[k * LDB + c * 8] = sh[idx];
            *(uint4*)&Bl[k * LDB + c * 8] = sl[idx];
        }
        __syncthreads();

#pragma unroll
        for (int ks = 0; ks < 8; ks++) {
            int k0 = ks * 16;
            wmma::fragment<wmma::matrix_a, 16, 16, 16, __nv_bfloat16, wmma::row_major> ah[2], al[2];
#pragma unroll
            for (int i = 0; i < 2; i++) {
                wmma::load_matrix_sync(ah[i], Ah + (wy * 32 + i * 16) * LDA + k0, LDA);
                wmma::load_matrix_sync(al[i], Al + (wy * 32 + i * 16) * LDA + k0, LDA);
            }
#pragma unroll
            for (int j = 0; j < 4; j++) {
                int n0 = wx * 64 + j * 16;
                wmma::fragment<wmma::matrix_b, 16, 16, 16, __nv_bfloat16, wmma::row_major> bh, bl;
                wmma::load_matrix_sync(bh, Bh + k0 * LDB + n0, LDB);
                wmma::load_matrix_sync(bl, Bl + k0 * LDB + n0, LDB);
#pragma unroll
                for (int i = 0; i < 2; i++) {
                    wmma::mma_sync(acc[i][j], ah[i], bh, acc[i][j]);
                    wmma::mma_sync(acc[i][j], ah[i], bl, acc[i][j]);
                    wmma::mma_sync(acc[i][j], al[i], bh, acc[i][j]);
                }
            }
        }
    }

    // ---- epilogue ----
    if (LAYER == 1) {
#pragma unroll
        for (int i = 0; i < 2; i++)
#pragma unroll
            for (int j = 0; j < 4; j++)
#pragma unroll
                for (int t = 0; t < acc[i][j].num_elements; t++)
                    acc[i][j].x[t] = fmaxf(acc[i][j].x[t], 0.f);
        // bounce via smem, then dual-write fp32 g_h + fp16 g_hh
        float* bounce = (float*)smem;
        __syncthreads();
#pragma unroll
        for (int i = 0; i < 2; i++)
#pragma unroll
            for (int j = 0; j < 4; j++)
                wmma::store_matrix_sync(
                    bounce + (size_t)(wy * 32 + i * 16) * LDC + wx * 64 + j * 16,
                    acc[i][j], LDC, wmma::mem_row_major);
        __syncthreads();
        for (int idx = tid; idx < 128 * 32; idx += 256) {
            int r = idx >> 5, q = idx & 31;
            float4 v = *(float4*)&bounce[r * LDC + q * 4];
            *(float4*)(out + (size_t)(row0 + r) * D + q * 4) = v;
            __half2 p0 = __floats2half2_rn(v.x, v.y);
            __half2 p1 = __floats2half2_rn(v.z, v.w);
            uint2 hv;
            hv.x = *(uint32_t*)&p0; hv.y = *(uint32_t*)&p1;
            *(uint2*)(&g_hh[(size_t)(row0 + r) * D + q * 4]) = hv;
        }
        return;
    }

    bool direct = (row0 + 128 <= N_NODES);
    if (direct) {
#pragma unroll
        for (int i = 0; i < 2; i++)
#pragma unroll
            for (int j = 0; j < 4; j++)
                wmma::store_matrix_sync(
                    out + (size_t)(row0 + wy * 32 + i * 16) * D + wx * 64 + j * 16,
                    acc[i][j], D, wmma::mem_row_major);
    } else {
        float* bounce = (float*)smem;
        __syncthreads();
#pragma unroll
        for (int i = 0; i < 2; i++)
#pragma unroll
            for (int j = 0; j < 4; j++)
                wmma::store_matrix_sync(
                    bounce + (size_t)(wy * 32 + i * 16) * LDC + wx * 64 + j * 16,
                    acc[i][j], LDC, wmma::mem_row_major);
        __syncthreads();
        int valid = N_NODES - row0;
        for (int idx = tid; idx < valid * 32; idx += 256) {
            int r = idx >> 5, q = idx & 31;
            float4 v = *(float4*)&bounce[r * LDC + q * 4];
            *(float4*)(out + (size_t)(row0 + r) * D + q * 4) = v;
        }
    }
}

// ---------------- launch ----------------
extern "C" void kernel_launch(void* const* d_in, const int* in_sizes, int n_in,
                              void* d_out, int out_size)
{
    const float* x   = (const float*)d_in[0];
    const float* W1l = (const float*)d_in[1];
    const float* b1  = (const float*)d_in[2];
    const float* W1r = (const float*)d_in[3];
    const float* W2l = (const float*)d_in[4];
    const float* b2  = (const float*)d_in[5];
    const float* W2r = (const float*)d_in[6];
    const int*   ei  = (const int*)d_in[7];
    float* out = (float*)d_out;

    const int TB = 256;
    cudaFuncSetAttribute(k_wgemm<1>, cudaFuncAttributeMaxDynamicSharedMemorySize, SMEM_REQ);
    cudaFuncSetAttribute(k_wgemm<2>, cudaFuncAttributeMaxDynamicSharedMemorySize, SMEM_REQ);

    const int aggBlocks  = (N_NODES * 32 + TB - 1) / TB;
    const int gemmBlocks = (N_NODES + 127) / 128;

    k_init<<<ZB + WB + EB + XB, TB>>>(x, W1l, W1r, W2l, W2r, ei,
                                      out + (size_t)N_NODES * D);
    k_hist<<<(N_EDGES + TB - 1) / TB, TB>>>(ei);
    k_scan<<<1, 1024>>>();
    k_fill<<<(N_EDGES + TB - 1) / TB, TB>>>(ei);

    k_agg<1><<<aggBlocks, TB>>>();
    k_wgemm<1><<<gemmBlocks, TB, SMEM_REQ>>>(x, b1, nullptr, 0, 1);

    k_agg<2><<<aggBlocks, TB>>>();
    k_wgemm<2><<<gemmBlocks, TB, SMEM_REQ>>>(nullptr, b2, out, 2, 3);
}

// round 7
// speedup vs baseline: 2.3969x; 1.3527x over previous
#include <cuda_runtime.h>
#include <cuda_fp16.h>
#include <mma.h>
#include <cstdint>

using namespace nvcuda;

#define N_NODES 100000
#define N_PAD   100096          /* 782 * 128 */
#define N_EDGES 1600000
#define D 128

// ---------------- scratch (device globals; no allocation allowed) ----------------
__device__ int    g_deg[N_NODES];
__device__ int    g_fill[N_NODES];
__device__ int    g_rowptr[N_NODES + 1];
__device__ int    g_csr_src[N_EDGES];
__device__ __align__(16) __half g_xh[(size_t)N_PAD * D];    // x   (fp16)
__device__ __align__(16) __half g_hh[(size_t)N_PAD * D];    // h   (fp16)
__device__ __align__(16) __half g_aggh[(size_t)N_PAD * D];  // agg (fp16)
// weight images: [mat 0..3][hi=0/lo=1][K=128][N=128] fp16 row-major
__device__ __align__(16) __half g_Wimg[4][2][128 * 128];

// ---------------- mega-init: zero + weight prep + edgecast + x->fp16 ----------------
#define ZB 391
#define WB 4
#define EB 3125     /* 3.2M floats / 1024 per block */
#define XB 6250     /* 12.8M floats / 2048 per block */

__global__ void k_init(const float* __restrict__ x,
                       const float* __restrict__ W0, const float* __restrict__ W1,
                       const float* __restrict__ W2, const float* __restrict__ W3,
                       const int* __restrict__ ei, float* __restrict__ outTail)
{
    int b = blockIdx.x;
    int tid = threadIdx.x;
    if (b < ZB) {
        int i = b * 256 + tid;
        if (i < N_NODES) { g_deg[i] = 0; g_fill[i] = 0; }
    } else if (b < ZB + WB) {
        int m = b - ZB;
        const float* W = (m == 0) ? W0 : (m == 1) ? W1 : (m == 2) ? W2 : W3;
        __half* hi = &g_Wimg[m][0][0];
        __half* lo = &g_Wimg[m][1][0];
        for (int idx = tid; idx < 128 * 128; idx += 256) {
            float v = W[idx];
            __half h = __float2half_rn(v);
            hi[idx] = h;
            lo[idx] = __float2half_rn(v - __half2float(h));
        }
    } else if (b < ZB + WB + EB) {
        int i = (b - ZB - WB) * 1024 + tid * 4;
        int4 v = *(const int4*)(ei + i);
        *(float4*)(outTail + i) = make_float4((float)v.x, (float)v.y,
                                              (float)v.z, (float)v.w);
    } else {
        int b2 = b - ZB - WB - EB;
        const float4* xv = (const float4*)x;
        int f4 = b2 * 512 + tid * 2;
        float4 a = xv[f4], c = xv[f4 + 1];
        __half2 h0 = __floats2half2_rn(a.x, a.y);
        __half2 h1 = __floats2half2_rn(a.z, a.w);
        __half2 h2 = __floats2half2_rn(c.x, c.y);
        __half2 h3 = __floats2half2_rn(c.z, c.w);
        uint4 o;
        o.x = *(uint32_t*)&h0; o.y = *(uint32_t*)&h1;
        o.z = *(uint32_t*)&h2; o.w = *(uint32_t*)&h3;
        *(uint4*)(&g_xh[(size_t)b2 * 2048 + tid * 8]) = o;
    }
}

// ---------------- CSR build ----------------
__global__ void k_hist(const int* __restrict__ ei) {
    int e = blockIdx.x * blockDim.x + threadIdx.x;
    if (e < N_EDGES) atomicAdd(&g_deg[ei[N_EDGES + e]], 1);
}
__global__ void k_scan() {
    __shared__ int ss[1024];
    int t = threadIdx.x;
    const int CH = (N_NODES + 1023) / 1024;
    int b0 = t * CH, b1 = min(b0 + CH, N_NODES);
    int s = 0;
    for (int i = b0; i < b1; i++) s += g_deg[i];
    ss[t] = s; __syncthreads();
    for (int off = 1; off < 1024; off <<= 1) {
        int v = (t >= off) ? ss[t - off] : 0;
        __syncthreads(); ss[t] += v; __syncthreads();
    }
    int excl = (t == 0) ? 0 : ss[t - 1];
    for (int i = b0; i < b1; i++) { g_rowptr[i] = excl; excl += g_deg[i]; }
    if (t == 1023) g_rowptr[N_NODES] = excl;
}
__global__ void k_fill(const int* __restrict__ ei) {
    int e = blockIdx.x * blockDim.x + threadIdx.x;
    if (e < N_EDGES) {
        int dst = ei[N_EDGES + e];
        int p = atomicAdd(&g_fill[dst], 1);
        g_csr_src[g_rowptr[dst] + p] = ei[e];
    }
}

// ---------------- mean aggregation (fp16 in, fp16 out): one warp per node ---------
template <int LAYER>
__global__ void k_agg() {
    const uint2* __restrict__ xin =
        (const uint2*)((LAYER == 1) ? g_xh : g_hh);   // 32 uint2 per row
    int gw = (blockIdx.x * blockDim.x + threadIdx.x) >> 5;
    int lane = threadIdx.x & 31;
    if (gw >= N_NODES) return;
    int e0 = g_rowptr[gw], e1 = g_rowptr[gw + 1];
    float4 a0 = make_float4(0.f, 0.f, 0.f, 0.f);
    float4 a1 = make_float4(0.f, 0.f, 0.f, 0.f);
    int e = e0;
    for (; e + 1 < e1; e += 2) {
        int s0 = g_csr_src[e], s1 = g_csr_src[e + 1];
        uint2 v0 = xin[(size_t)s0 * 32 + lane];
        uint2 v1 = xin[(size_t)s1 * 32 + lane];
        float2 f00 = __half22float2(*(__half2*)&v0.x);
        float2 f01 = __half22float2(*(__half2*)&v0.y);
        float2 f10 = __half22float2(*(__half2*)&v1.x);
        float2 f11 = __half22float2(*(__half2*)&v1.y);
        a0.x += f00.x; a0.y += f00.y; a0.z += f01.x; a0.w += f01.y;
        a1.x += f10.x; a1.y += f10.y; a1.z += f11.x; a1.w += f11.y;
    }
    if (e < e1) {
        int s0 = g_csr_src[e];
        uint2 v0 = xin[(size_t)s0 * 32 + lane];
        float2 f00 = __half22float2(*(__half2*)&v0.x);
        float2 f01 = __half22float2(*(__half2*)&v0.y);
        a0.x += f00.x; a0.y += f00.y; a0.z += f01.x; a0.w += f01.y;
    }
    int d = e1 - e0;
    float di = (d > 0) ? (1.0f / (float)d) : 0.0f;
    __half2 p0 = __floats2half2_rn((a0.x + a1.x) * di, (a0.y + a1.y) * di);
    __half2 p1 = __floats2half2_rn((a0.z + a1.z) * di, (a0.w + a1.w) * di);
    uint2 o;
    o.x = *(uint32_t*)&p0; o.y = *(uint32_t*)&p1;
    *(uint2*)(&g_aggh[(size_t)gw * D + lane * 4]) = o;
}

// ---------------- WMMA fp16 2-term fused SAGE linear ----------------
// out[128x128] = agg@Wl + root@Wr + bias (+ReLU layer1)
// A fp16 single, B fp16 hi+lo. 8 warps 4x2; each warp 2x4 frags (32x64).
#define LDA 136
#define LDB 136
#define LDC 132
#define SM_BIAS   (16 * 136 * 4)                 /* 8704 */
#define SM_TILE   (128 * 136 * 2)                /* 34816 */
#define SMEM_REQ  (SM_BIAS + 3 * SM_TILE)        /* 113152 */

template <int LAYER>
__global__ void __launch_bounds__(256, 2) k_wgemm(
    const float* __restrict__ bias,
    float* __restrict__ OutExt)
{
    extern __shared__ char smem[];
    float* bias_rep = (float*)smem;
    __half* As = (__half*)(smem + SM_BIAS);
    __half* Bh = As + 128 * LDA;
    __half* Bl = Bh + 128 * LDB;

    const int tid = threadIdx.x;
    const int wid = tid >> 5;
    const int row0 = blockIdx.x * 128;
    const int wy = wid >> 1;
    const int wx = wid & 1;

    for (int i = tid; i < 16 * 128; i += 256) {
        int r = i >> 7, c = i & 127;
        bias_rep[r * 136 + c] = bias[c];
    }
    __syncthreads();

    wmma::fragment<wmma::accumulator, 16, 16, 16, float> acc[2][4];
#pragma unroll
    for (int i = 0; i < 2; i++)
#pragma unroll
        for (int j = 0; j < 4; j++)
            wmma::load_matrix_sync(acc[i][j], bias_rep + wx * 64 + j * 16, 136,
                                   wmma::mem_row_major);

    const int wl = (LAYER == 1) ? 0 : 2;
#pragma unroll 1
    for (int side = 0; side < 2; side++) {
        if (side == 1) __syncthreads();
        const __half* __restrict__ Asrc =
            (side == 0) ? g_aggh : ((LAYER == 1) ? g_xh : g_hh);
        // A tile: straight fp16 copy (padded buffers -> no guards)
        const uint4* av = (const uint4*)(Asrc + (size_t)row0 * D);
#pragma unroll
        for (int it = 0; it < 8; it++) {
            int idx = tid + it * 256;            // 2048 uint4 (8 halves each)
            int m = idx >> 4, c = idx & 15;
            *(uint4*)&As[m * LDA + c * 8] = av[idx];
        }
        // B tiles
        const uint4* sh = (const uint4*)&g_Wimg[wl + side][0][0];
        const uint4* sl = (const uint4*)&g_Wimg[wl + side][1][0];
#pragma unroll
        for (int it = 0; it < 8; it++) {
            int idx = tid + it * 256;
            int k = idx >> 4, c = idx & 15;
            *(uint4*)&Bh[k * LDB + c * 8] = sh[idx];
            *(uint4*)&Bl[k * LDB + c * 8] = sl[idx];
        }
        __syncthreads();

#pragma unroll
        for (int ks = 0; ks < 8; ks++) {
            int k0 = ks * 16;
            wmma::fragment<wmma::matrix_a, 16, 16, 16, __half, wmma::row_major> a[2];
#pragma unroll
            for (int i = 0; i < 2; i++)
                wmma::load_matrix_sync(a[i], As + (wy * 32 + i * 16) * LDA + k0, LDA);
#pragma unroll
            for (int j = 0; j < 4; j++) {
                int n0 = wx * 64 + j * 16;
                wmma::fragment<wmma::matrix_b, 16, 16, 16, __half, wmma::row_major> bh, bl;
                wmma::load_matrix_sync(bh, Bh + k0 * LDB + n0, LDB);
                wmma::load_matrix_sync(bl, Bl + k0 * LDB + n0, LDB);
#pragma unroll
                for (int i = 0; i < 2; i++) {
                    wmma::mma_sync(acc[i][j], a[i], bh, acc[i][j]);
                    wmma::mma_sync(acc[i][j], a[i], bl, acc[i][j]);
                }
            }
        }
    }

    // ---- epilogue ----
    if (LAYER == 1) {
#pragma unroll
        for (int i = 0; i < 2; i++)
#pragma unroll
            for (int j = 0; j < 4; j++)
#pragma unroll
                for (int t = 0; t < acc[i][j].num_elements; t++)
                    acc[i][j].x[t] = fmaxf(acc[i][j].x[t], 0.f);
        // bounce via smem, write fp16 g_hh (padded -> unguarded)
        float* bounce = (float*)smem;
        __syncthreads();
#pragma unroll
        for (int i = 0; i < 2; i++)
#pragma unroll
            for (int j = 0; j < 4; j++)
                wmma::store_matrix_sync(
                    bounce + (size_t)(wy * 32 + i * 16) * LDC + wx * 64 + j * 16,
                    acc[i][j], LDC, wmma::mem_row_major);
        __syncthreads();
        for (int idx = tid; idx < 128 * 32; idx += 256) {
            int r = idx >> 5, q = idx & 31;
            float4 v = *(float4*)&bounce[r * LDC + q * 4];
            __half2 p0 = __floats2half2_rn(v.x, v.y);
            __half2 p1 = __floats2half2_rn(v.z, v.w);
            uint2 hv;
            hv.x = *(uint32_t*)&p0; hv.y = *(uint32_t*)&p1;
            *(uint2*)(&g_hh[(size_t)(row0 + r) * D + q * 4]) = hv;
        }
        return;
    }

    bool direct = (row0 + 128 <= N_NODES);
    if (direct) {
#pragma unroll
        for (int i = 0; i < 2; i++)
#pragma unroll
            for (int j = 0; j < 4; j++)
                wmma::store_matrix_sync(
                    OutExt + (size_t)(row0 + wy * 32 + i * 16) * D + wx * 64 + j * 16,
                    acc[i][j], D, wmma::mem_row_major);
    } else {
        float* bounce = (float*)smem;
        __syncthreads();
#pragma unroll
        for (int i = 0; i < 2; i++)
#pragma unroll
            for (int j = 0; j < 4; j++)
                wmma::store_matrix_sync(
                    bounce + (size_t)(wy * 32 + i * 16) * LDC + wx * 64 + j * 16,
                    acc[i][j], LDC, wmma::mem_row_major);
        __syncthreads();
        int valid = N_NODES - row0;
        for (int idx = tid; idx < valid * 32; idx += 256) {
            int r = idx >> 5, q = idx & 31;
            float4 v = *(float4*)&bounce[r * LDC + q * 4];
            *(float4*)(OutExt + (size_t)(row0 + r) * D + q * 4) = v;
        }
    }
}

// ---------------- launch ----------------
extern "C" void kernel_launch(void* const* d_in, const int* in_sizes, int n_in,
                              void* d_out, int out_size)
{
    const float* x   = (const float*)d_in[0];
    const float* W1l = (const float*)d_in[1];
    const float* b1  = (const float*)d_in[2];
    const float* W1r = (const float*)d_in[3];
    const float* W2l = (const float*)d_in[4];
    const float* b2  = (const float*)d_in[5];
    const float* W2r = (const float*)d_in[6];
    const int*   ei  = (const int*)d_in[7];
    float* out = (float*)d_out;

    const int TB = 256;
    cudaFuncSetAttribute(k_wgemm<1>, cudaFuncAttributeMaxDynamicSharedMemorySize, SMEM_REQ);
    cudaFuncSetAttribute(k_wgemm<2>, cudaFuncAttributeMaxDynamicSharedMemorySize, SMEM_REQ);

    const int aggBlocks  = (N_NODES * 32 + TB - 1) / TB;
    const int gemmBlocks = (N_NODES + 127) / 128;   // 782

    k_init<<<ZB + WB + EB + XB, TB>>>(x, W1l, W1r, W2l, W2r, ei,
                                      out + (size_t)N_NODES * D);
    k_hist<<<(N_EDGES + TB - 1) / TB, TB>>>(ei);
    k_scan<<<1, 1024>>>();
    k_fill<<<(N_EDGES + TB - 1) / TB, TB>>>(ei);

    k_agg<1><<<aggBlocks, TB>>>();
    k_wgemm<1><<<gemmBlocks, TB, SMEM_REQ>>>(b1, nullptr);

    k_agg<2><<<aggBlocks, TB>>>();
    k_wgemm<2><<<gemmBlocks, TB, SMEM_REQ>>>(b2, out);
}

// round 8
// speedup vs baseline: 2.6717x; 1.1146x over previous
#include <cuda_runtime.h>
#include <cuda_fp16.h>
#include <mma.h>
#include <cstdint>

using namespace nvcuda;

#define N_NODES 100000
#define N_PAD   100096          /* 782 * 128 */
#define N_EDGES 1600000
#define D 128

// ---------------- scratch (device globals; no allocation allowed) ----------------
__device__ int    g_deg[N_NODES];
__device__ int    g_fill[N_NODES];
__device__ int    g_rowptr[N_NODES + 1];
__device__ int    g_csr_src[N_EDGES];
__device__ __align__(16) __half g_xh[(size_t)N_PAD * D];    // x   (fp16)
__device__ __align__(16) __half g_hh[(size_t)N_PAD * D];    // h   (fp16)
__device__ __align__(16) __half g_aggh[(size_t)N_PAD * D];  // agg (fp16)
// weight images: [mat 0..3][K=128][N=128] fp16 row-major
__device__ __align__(16) __half g_Wimg[4][128 * 128];

// ---------------- mega-init: zero + weight prep + edgecast + x->fp16 ----------------
#define ZB 391
#define WB 4
#define EB 3125     /* 3.2M floats / 1024 per block */
#define XB 6250     /* 12.8M floats / 2048 per block */

__global__ void k_init(const float* __restrict__ x,
                       const float* __restrict__ W0, const float* __restrict__ W1,
                       const float* __restrict__ W2, const float* __restrict__ W3,
                       const int* __restrict__ ei, float* __restrict__ outTail)
{
    int b = blockIdx.x;
    int tid = threadIdx.x;
    if (b < ZB) {
        int i = b * 256 + tid;
        if (i < N_NODES) { g_deg[i] = 0; g_fill[i] = 0; }
    } else if (b < ZB + WB) {
        int m = b - ZB;
        const float* W = (m == 0) ? W0 : (m == 1) ? W1 : (m == 2) ? W2 : W3;
        __half* hi = &g_Wimg[m][0];
        for (int idx = tid; idx < 128 * 128; idx += 256)
            hi[idx] = __float2half_rn(W[idx]);
    } else if (b < ZB + WB + EB) {
        int i = (b - ZB - WB) * 1024 + tid * 4;
        int4 v = *(const int4*)(ei + i);
        *(float4*)(outTail + i) = make_float4((float)v.x, (float)v.y,
                                              (float)v.z, (float)v.w);
    } else {
        int b2 = b - ZB - WB - EB;
        const float4* xv = (const float4*)x;
        int f4 = b2 * 512 + tid * 2;
        float4 a = xv[f4], c = xv[f4 + 1];
        __half2 h0 = __floats2half2_rn(a.x, a.y);
        __half2 h1 = __floats2half2_rn(a.z, a.w);
        __half2 h2 = __floats2half2_rn(c.x, c.y);
        __half2 h3 = __floats2half2_rn(c.z, c.w);
        uint4 o;
        o.x = *(uint32_t*)&h0; o.y = *(uint32_t*)&h1;
        o.z = *(uint32_t*)&h2; o.w = *(uint32_t*)&h3;
        *(uint4*)(&g_xh[(size_t)b2 * 2048 + tid * 8]) = o;
    }
}

// ---------------- CSR build ----------------
__global__ void k_hist(const int* __restrict__ ei) {
    int e = blockIdx.x * blockDim.x + threadIdx.x;
    if (e < N_EDGES) atomicAdd(&g_deg[ei[N_EDGES + e]], 1);
}
__global__ void k_scan() {
    __shared__ int ss[1024];
    int t = threadIdx.x;
    const int CH = (N_NODES + 1023) / 1024;
    int b0 = t * CH, b1 = min(b0 + CH, N_NODES);
    int s = 0;
    for (int i = b0; i < b1; i++) s += g_deg[i];
    ss[t] = s; __syncthreads();
    for (int off = 1; off < 1024; off <<= 1) {
        int v = (t >= off) ? ss[t - off] : 0;
        __syncthreads(); ss[t] += v; __syncthreads();
    }
    int excl = (t == 0) ? 0 : ss[t - 1];
    for (int i = b0; i < b1; i++) { g_rowptr[i] = excl; excl += g_deg[i]; }
    if (t == 1023) g_rowptr[N_NODES] = excl;
}
__global__ void k_fill(const int* __restrict__ ei) {
    int e = blockIdx.x * blockDim.x + threadIdx.x;
    if (e < N_EDGES) {
        int dst = ei[N_EDGES + e];
        int p = atomicAdd(&g_fill[dst], 1);
        g_csr_src[g_rowptr[dst] + p] = ei[e];
    }
}

// ---------------- mean aggregation (fp16 in/out), 4-edge MLP, warp/node ----------
template <int LAYER>
__global__ void k_agg() {
    const uint2* __restrict__ xin =
        (const uint2*)((LAYER == 1) ? g_xh : g_hh);   // 32 uint2 per row
    int gw = (blockIdx.x * blockDim.x + threadIdx.x) >> 5;
    int lane = threadIdx.x & 31;
    if (gw >= N_NODES) return;
    int e0 = g_rowptr[gw], e1 = g_rowptr[gw + 1];
    float4 a0 = make_float4(0.f, 0.f, 0.f, 0.f);
    float4 a1 = make_float4(0.f, 0.f, 0.f, 0.f);
    int e = e0;
    for (; e + 3 < e1; e += 4) {
        int s0 = g_csr_src[e],     s1 = g_csr_src[e + 1];
        int s2 = g_csr_src[e + 2], s3 = g_csr_src[e + 3];
        uint2 v0 = xin[(size_t)s0 * 32 + lane];
        uint2 v1 = xin[(size_t)s1 * 32 + lane];
        uint2 v2 = xin[(size_t)s2 * 32 + lane];
        uint2 v3 = xin[(size_t)s3 * 32 + lane];
        float2 f;
        f = __half22float2(*(__half2*)&v0.x); a0.x += f.x; a0.y += f.y;
        f = __half22float2(*(__half2*)&v0.y); a0.z += f.x; a0.w += f.y;
        f = __half22float2(*(__half2*)&v1.x); a1.x += f.x; a1.y += f.y;
        f = __half22float2(*(__half2*)&v1.y); a1.z += f.x; a1.w += f.y;
        f = __half22float2(*(__half2*)&v2.x); a0.x += f.x; a0.y += f.y;
        f = __half22float2(*(__half2*)&v2.y); a0.z += f.x; a0.w += f.y;
        f = __half22float2(*(__half2*)&v3.x); a1.x += f.x; a1.y += f.y;
        f = __half22float2(*(__half2*)&v3.y); a1.z += f.x; a1.w += f.y;
    }
    for (; e < e1; e++) {
        int s0 = g_csr_src[e];
        uint2 v0 = xin[(size_t)s0 * 32 + lane];
        float2 f;
        f = __half22float2(*(__half2*)&v0.x); a0.x += f.x; a0.y += f.y;
        f = __half22float2(*(__half2*)&v0.y); a0.z += f.x; a0.w += f.y;
    }
    int d = e1 - e0;
    float di = (d > 0) ? (1.0f / (float)d) : 0.0f;
    __half2 p0 = __floats2half2_rn((a0.x + a1.x) * di, (a0.y + a1.y) * di);
    __half2 p1 = __floats2half2_rn((a0.z + a1.z) * di, (a0.w + a1.w) * di);
    uint2 o;
    o.x = *(uint32_t*)&p0; o.y = *(uint32_t*)&p1;
    *(uint2*)(&g_aggh[(size_t)gw * D + lane * 4]) = o;
}

// ---------------- WMMA fp16 single-term fused SAGE linear ----------------
// out[128x128] = agg@Wl + root@Wr + bias (+ReLU layer1); A,B plain fp16.
#define LDA 136
#define LDB 136
#define LDC 132
#define SM_BIAS   (16 * 136 * 4)                 /* 8704 */
#define SM_TILE   (128 * 136 * 2)                /* 34816 */
#define SMEM_REQ  (SM_BIAS + 2 * SM_TILE)        /* 78336 */

template <int LAYER>
__global__ void __launch_bounds__(256, 2) k_wgemm(
    const float* __restrict__ bias,
    float* __restrict__ OutExt)
{
    extern __shared__ char smem[];
    float* bias_rep = (float*)smem;
    __half* As = (__half*)(smem + SM_BIAS);
    __half* Bs = As + 128 * LDA;

    const int tid = threadIdx.x;
    const int wid = tid >> 5;
    const int row0 = blockIdx.x * 128;
    const int wy = wid >> 1;
    const int wx = wid & 1;

    for (int i = tid; i < 16 * 128; i += 256) {
        int r = i >> 7, c = i & 127;
        bias_rep[r * 136 + c] = bias[c];
    }
    __syncthreads();

    wmma::fragment<wmma::accumulator, 16, 16, 16, float> acc[2][4];
#pragma unroll
    for (int i = 0; i < 2; i++)
#pragma unroll
        for (int j = 0; j < 4; j++)
            wmma::load_matrix_sync(acc[i][j], bias_rep + wx * 64 + j * 16, 136,
                                   wmma::mem_row_major);

    const int wl = (LAYER == 1) ? 0 : 2;
#pragma unroll 1
    for (int side = 0; side < 2; side++) {
        if (side == 1) __syncthreads();
        const __half* __restrict__ Asrc =
            (side == 0) ? g_aggh : ((LAYER == 1) ? g_xh : g_hh);
        const uint4* av = (const uint4*)(Asrc + (size_t)row0 * D);
        const uint4* bv = (const uint4*)&g_Wimg[wl + side][0];
#pragma unroll
        for (int it = 0; it < 8; it++) {
            int idx = tid + it * 256;            // 2048 uint4 (8 halves each)
            int m = idx >> 4, c = idx & 15;
            *(uint4*)&As[m * LDA + c * 8] = av[idx];
            *(uint4*)&Bs[m * LDB + c * 8] = bv[idx];
        }
        __syncthreads();

#pragma unroll
        for (int ks = 0; ks < 8; ks++) {
            int k0 = ks * 16;
            wmma::fragment<wmma::matrix_a, 16, 16, 16, __half, wmma::row_major> a[2];
#pragma unroll
            for (int i = 0; i < 2; i++)
                wmma::load_matrix_sync(a[i], As + (wy * 32 + i * 16) * LDA + k0, LDA);
#pragma unroll
            for (int j = 0; j < 4; j++) {
                int n0 = wx * 64 + j * 16;
                wmma::fragment<wmma::matrix_b, 16, 16, 16, __half, wmma::row_major> b;
                wmma::load_matrix_sync(b, Bs + k0 * LDB + n0, LDB);
#pragma unroll
                for (int i = 0; i < 2; i++)
                    wmma::mma_sync(acc[i][j], a[i], b, acc[i][j]);
            }
        }
    }

    // ---- epilogue ----
    if (LAYER == 1) {
#pragma unroll
        for (int i = 0; i < 2; i++)
#pragma unroll
            for (int j = 0; j < 4; j++)
#pragma unroll
                for (int t = 0; t < acc[i][j].num_elements; t++)
                    acc[i][j].x[t] = fmaxf(acc[i][j].x[t], 0.f);
        float* bounce = (float*)smem;
        __syncthreads();
#pragma unroll
        for (int i = 0; i < 2; i++)
#pragma unroll
            for (int j = 0; j < 4; j++)
                wmma::store_matrix_sync(
                    bounce + (size_t)(wy * 32 + i * 16) * LDC + wx * 64 + j * 16,
                    acc[i][j], LDC, wmma::mem_row_major);
        __syncthreads();
        for (int idx = tid; idx < 128 * 32; idx += 256) {
            int r = idx >> 5, q = idx & 31;
            float4 v = *(float4*)&bounce[r * LDC + q * 4];
            __half2 p0 = __floats2half2_rn(v.x, v.y);
            __half2 p1 = __floats2half2_rn(v.z, v.w);
            uint2 hv;
            hv.x = *(uint32_t*)&p0; hv.y = *(uint32_t*)&p1;
            *(uint2*)(&g_hh[(size_t)(row0 + r) * D + q * 4]) = hv;
        }
        return;
    }

    bool direct = (row0 + 128 <= N_NODES);
    if (direct) {
#pragma unroll
        for (int i = 0; i < 2; i++)
#pragma unroll
            for (int j = 0; j < 4; j++)
                wmma::store_matrix_sync(
                    OutExt + (size_t)(row0 + wy * 32 + i * 16) * D + wx * 64 + j * 16,
                    acc[i][j], D, wmma::mem_row_major);
    } else {
        float* bounce = (float*)smem;
        __syncthreads();
#pragma unroll
        for (int i = 0; i < 2; i++)
#pragma unroll
            for (int j = 0; j < 4; j++)
                wmma::store_matrix_sync(
                    bounce + (size_t)(wy * 32 + i * 16) * LDC + wx * 64 + j * 16,
                    acc[i][j], LDC, wmma::mem_row_major);
        __syncthreads();
        int valid = N_NODES - row0;
        for (int idx = tid; idx < valid * 32; idx += 256) {
            int r = idx >> 5, q = idx & 31;
            float4 v = *(float4*)&bounce[r * LDC + q * 4];
            *(float4*)(OutExt + (size_t)(row0 + r) * D + q * 4) = v;
        }
    }
}

// ---------------- launch ----------------
extern "C" void kernel_launch(void* const* d_in, const int* in_sizes, int n_in,
                              void* d_out, int out_size)
{
    const float* x   = (const float*)d_in[0];
    const float* W1l = (const float*)d_in[1];
    const float* b1  = (const float*)d_in[2];
    const float* W1r = (const float*)d_in[3];
    const float* W2l = (const float*)d_in[4];
    const float* b2  = (const float*)d_in[5];
    const float* W2r = (const float*)d_in[6];
    const int*   ei  = (const int*)d_in[7];
    float* out = (float*)d_out;

    const int TB = 256;
    cudaFuncSetAttribute(k_wgemm<1>, cudaFuncAttributeMaxDynamicSharedMemorySize, SMEM_REQ);
    cudaFuncSetAttribute(k_wgemm<2>, cudaFuncAttributeMaxDynamicSharedMemorySize, SMEM_REQ);

    const int aggBlocks  = (N_NODES * 32 + TB - 1) / TB;
    const int gemmBlocks = (N_NODES + 127) / 128;   // 782

    k_init<<<ZB + WB + EB + XB, TB>>>(x, W1l, W1r, W2l, W2r, ei,
                                      out + (size_t)N_NODES * D);
    k_hist<<<(N_EDGES + TB - 1) / TB, TB>>>(ei);
    k_scan<<<1, 1024>>>();
    k_fill<<<(N_EDGES + TB - 1) / TB, TB>>>(ei);

    k_agg<1><<<aggBlocks, TB>>>();
    k_wgemm<1><<<gemmBlocks, TB, SMEM_REQ>>>(b1, nullptr);

    k_agg<2><<<aggBlocks, TB>>>();
    k_wgemm<2><<<gemmBlocks, TB, SMEM_REQ>>>(b2, out);
}